// round 3
// baseline (speedup 1.0000x reference)
#include <cuda_runtime.h>

// KANLinear fused kernel, round 3.
// Fix: s_rd1 needs 9 entries (b1[7] right-term uses rd1[8] = 1/(t9-t8));
// previous rounds read OOB shared memory for x in [t8, t9). Exact fp32 math
// (no TF32 rounding) to measure the true residual vs the reference.

#define NROWS 32768
#define FDIM  512
#define UDIM  512
#define NKNOT 10
#define KW    7            // values per feature: relu + 6 basis

#define TM 64
#define TN 128
#define KB 8               // features per k-chunk
#define KK (KB * KW)       // 56 k-indices per chunk
#define NCHUNK (FDIM / KB) // 64
#define SA_LD (TM + 4)     // padded lead dim for sA

__device__ float g_xn[(size_t)NROWS * FDIM];

// ---------------------------------------------------------------------------
// Kernel 1: LayerNorm (one row per block, 128 threads, float4 path)
// ---------------------------------------------------------------------------
__global__ __launch_bounds__(128) void ln_kernel(const float* __restrict__ x,
                                                 const float* __restrict__ gamma,
                                                 const float* __restrict__ beta) {
    int row = blockIdx.x;
    int tid = threadIdx.x;  // 128 threads * 4 floats = 512
    const float4* xr = reinterpret_cast<const float4*>(x + (size_t)row * FDIM);
    float4 v = xr[tid];

    __shared__ float red[4];
    __shared__ float red2[4];

    float s = v.x + v.y + v.z + v.w;
    #pragma unroll
    for (int o = 16; o > 0; o >>= 1) s += __shfl_xor_sync(0xffffffffu, s, o);
    if ((tid & 31) == 0) red[tid >> 5] = s;
    __syncthreads();
    float mean = (red[0] + red[1] + red[2] + red[3]) * (1.0f / FDIM);

    float dx = v.x - mean, dy = v.y - mean, dz = v.z - mean, dw = v.w - mean;
    float s2 = dx * dx + dy * dy + dz * dz + dw * dw;
    #pragma unroll
    for (int o = 16; o > 0; o >>= 1) s2 += __shfl_xor_sync(0xffffffffu, s2, o);
    if ((tid & 31) == 0) red2[tid >> 5] = s2;
    __syncthreads();
    float var = (red2[0] + red2[1] + red2[2] + red2[3]) * (1.0f / FDIM);
    float inv = rsqrtf(var + 1e-3f);

    float4 g = reinterpret_cast<const float4*>(gamma)[tid];
    float4 b = reinterpret_cast<const float4*>(beta)[tid];
    float4 o4;
    o4.x = dx * inv * g.x + b.x;
    o4.y = dy * inv * g.y + b.y;
    o4.z = dz * inv * g.z + b.z;
    o4.w = dw * inv * g.w + b.w;
    reinterpret_cast<float4*>(g_xn + (size_t)row * FDIM)[tid] = o4;
}

// ---------------------------------------------------------------------------
// Kernel 2: fused basis-gen + GEMM (exact fp32).
// Block computes out tile [TM=64 rows, TN=128 cols], 256 threads.
// Per thread: 4 rows x 8 cols register tile.
// ---------------------------------------------------------------------------
__global__ __launch_bounds__(256) void kan_gemm_kernel(
    const float* __restrict__ Wb,    // [F, U] base weight
    const float* __restrict__ bias,  // [U]
    const float* __restrict__ Ws,    // [F*6, U] spline weight
    const float* __restrict__ grid,  // [1, F, 10] (all features identical knots)
    float* __restrict__ out)         // [N, U]
{
    __shared__ float sA[KK * SA_LD];
    __shared__ float sB[KK * TN];
    __shared__ float s_t[NKNOT];
    __shared__ float s_rd1[9];         // 1/(t[j+1]-t[j]), j=0..8  (9 entries!)
    __shared__ float s_rd2[8];         // 1/(t[j+2]-t[j]), j=0..7
    __shared__ float s_rd3[7];         // 1/(t[j+3]-t[j]), j=0..6

    const int tid = threadIdx.x;
    const int col0 = blockIdx.x * TN;
    const int row0 = blockIdx.y * TM;

    if (tid < NKNOT) s_t[tid] = grid[tid];
    __syncthreads();
    if (tid < 9)       s_rd1[tid]      = 1.0f / (s_t[tid + 1]      - s_t[tid]);
    else if (tid < 17) s_rd2[tid - 9]  = 1.0f / (s_t[tid - 9 + 2]  - s_t[tid - 9]);
    else if (tid < 24) s_rd3[tid - 17] = 1.0f / (s_t[tid - 17 + 3] - s_t[tid - 17]);
    __syncthreads();

    const int ty = tid >> 4;
    const int tx = tid & 15;
    const int ry = ty * 4;
    const int cx = tx * 8;

    float acc[4][8];
    #pragma unroll
    for (int i = 0; i < 4; ++i)
        #pragma unroll
        for (int j = 0; j < 8; ++j) acc[i][j] = 0.0f;

    for (int ch = 0; ch < NCHUNK; ++ch) {
        const int f0 = ch * KB;

        // ---- fill sA: 64 rows x 8 features -> relu + 6 basis each ----
        #pragma unroll
        for (int it = 0; it < (TM * KB) / 256; ++it) {  // 2 iterations
            int p  = tid + it * 256;
            int fl = p & (KB - 1);
            int r  = p >> 3;
            float xv = g_xn[(size_t)(row0 + r) * FDIM + f0 + fl];

            // Cox-de Boor, order 3, replicating the reference exactly
            float b0[9];
            #pragma unroll
            for (int j = 0; j < 9; ++j)
                b0[j] = (xv >= s_t[j] && xv < s_t[j + 1]) ? 1.0f : 0.0f;
            float b1[8];
            #pragma unroll
            for (int j = 0; j < 8; ++j)
                b1[j] = (xv - s_t[j]) * s_rd1[j] * b0[j] +
                        (s_t[j + 2] - xv) * s_rd1[j + 1] * b0[j + 1];
            float b2[7];
            #pragma unroll
            for (int j = 0; j < 7; ++j)
                b2[j] = (xv - s_t[j]) * s_rd2[j] * b1[j] +
                        (s_t[j + 3] - xv) * s_rd2[j + 1] * b1[j + 1];
            float b3[6];
            #pragma unroll
            for (int j = 0; j < 6; ++j)
                b3[j] = (xv - s_t[j]) * s_rd3[j] * b2[j] +
                        (s_t[j + 4] - xv) * s_rd3[j + 1] * b2[j + 1];

            float* a = &sA[(fl * KW) * SA_LD + r];
            a[0 * SA_LD] = fmaxf(xv, 0.0f);
            #pragma unroll
            for (int j = 0; j < 6; ++j) a[(j + 1) * SA_LD] = b3[j];
        }

        // ---- fill sB: KK rows x TN cols (float4) ----
        #pragma unroll
        for (int i = tid; i < KK * (TN / 4); i += 256) {  // 7 iterations
            int j  = i >> 5;
            int c4 = i & 31;
            int fl = j / KW;
            int m  = j - fl * KW;
            const float* src = (m == 0)
                ? (Wb + (size_t)(f0 + fl) * UDIM)
                : (Ws + (size_t)((f0 + fl) * 6 + (m - 1)) * UDIM);
            float4 v = *reinterpret_cast<const float4*>(src + col0 + c4 * 4);
            *reinterpret_cast<float4*>(&sB[j * TN + c4 * 4]) = v;
        }

        __syncthreads();

        // ---- compute ----
        #pragma unroll 4
        for (int kk = 0; kk < KK; ++kk) {
            float4 a4  = *reinterpret_cast<const float4*>(&sA[kk * SA_LD + ry]);
            float4 bL  = *reinterpret_cast<const float4*>(&sB[kk * TN + cx]);
            float4 bH  = *reinterpret_cast<const float4*>(&sB[kk * TN + cx + 4]);
            float av[4] = {a4.x, a4.y, a4.z, a4.w};
            float bv[8] = {bL.x, bL.y, bL.z, bL.w, bH.x, bH.y, bH.z, bH.w};
            #pragma unroll
            for (int i = 0; i < 4; ++i)
                #pragma unroll
                for (int j = 0; j < 8; ++j)
                    acc[i][j] = fmaf(av[i], bv[j], acc[i][j]);
        }

        __syncthreads();
    }

    // ---- epilogue: add base bias, store ----
    float4 bsL = *reinterpret_cast<const float4*>(bias + col0 + cx);
    float4 bsH = *reinterpret_cast<const float4*>(bias + col0 + cx + 4);
    #pragma unroll
    for (int i = 0; i < 4; ++i) {
        float4 oL, oH;
        oL.x = acc[i][0] + bsL.x;
        oL.y = acc[i][1] + bsL.y;
        oL.z = acc[i][2] + bsL.z;
        oL.w = acc[i][3] + bsL.w;
        oH.x = acc[i][4] + bsH.x;
        oH.y = acc[i][5] + bsH.y;
        oH.z = acc[i][6] + bsH.z;
        oH.w = acc[i][7] + bsH.w;
        float* dst = out + (size_t)(row0 + ry + i) * UDIM + col0 + cx;
        *reinterpret_cast<float4*>(dst)     = oL;
        *reinterpret_cast<float4*>(dst + 4) = oH;
    }
}

// ---------------------------------------------------------------------------
extern "C" void kernel_launch(void* const* d_in, const int* in_sizes, int n_in,
                              void* d_out, int out_size) {
    const float* x     = (const float*)d_in[0];  // [N, F]
    const float* gamma = (const float*)d_in[1];  // [F]
    const float* beta  = (const float*)d_in[2];  // [F]
    const float* Wb    = (const float*)d_in[3];  // [F, U]
    const float* bias  = (const float*)d_in[4];  // [U]
    const float* Ws    = (const float*)d_in[5];  // [F*6, U]
    const float* grid  = (const float*)d_in[6];  // [1, F, 10]
    float* out = (float*)d_out;

    ln_kernel<<<NROWS, 128>>>(x, gamma, beta);

    dim3 g(UDIM / TN, NROWS / TM);   // (4, 512)
    kan_gemm_kernel<<<g, 256>>>(Wb, bias, Ws, grid, out);
}

// round 5
// speedup vs baseline: 2.2434x; 2.2434x over previous
#include <cuda_runtime.h>
#include <cstdint>

// KANLinear, round 5: legacy mma.sync m16n8k8 TF32 (plain sm_103 target —
// tcgen05 unavailable in this harness's ptxas pass).
// Fused GEMM: A[32768,4096] (gen on the fly: relu + 4-nonzero cubic basis
// in 6 slots + pad0 per feature) @ B^T with B pre-fragmented in gmem.

#define NROWS 32768
#define FDIM  512
#define UDIM  512
#define KTOT  4096
#define NCHUNK 128          // chunks of K=32 (4 features)

__device__ float g_xn [(size_t)NROWS * FDIM];            // 64 MB LN output
__device__ float g_btf[(size_t)64 * 512 * 32 * 2];       // 8 MB frag-ordered B

__device__ __forceinline__ float to_tf32(float x) {
    float r;
    asm("cvt.rna.tf32.f32 %0, %1;" : "=f"(r) : "f"(x));
    return r;
}

// ---------------------------------------------------------------------------
// Kernel 1: LayerNorm (identical to the round-3 passing version)
// ---------------------------------------------------------------------------
__global__ __launch_bounds__(128) void ln_kernel(const float* __restrict__ x,
                                                 const float* __restrict__ gamma,
                                                 const float* __restrict__ beta) {
    int row = blockIdx.x, tid = threadIdx.x;
    const float4* xr = reinterpret_cast<const float4*>(x + (size_t)row * FDIM);
    float4 v = xr[tid];
    __shared__ float red[4], red2[4];
    float s = v.x + v.y + v.z + v.w;
    #pragma unroll
    for (int o = 16; o > 0; o >>= 1) s += __shfl_xor_sync(~0u, s, o);
    if ((tid & 31) == 0) red[tid >> 5] = s;
    __syncthreads();
    float mean = (red[0] + red[1] + red[2] + red[3]) * (1.0f / FDIM);
    float dx = v.x - mean, dy = v.y - mean, dz = v.z - mean, dw = v.w - mean;
    float s2 = dx * dx + dy * dy + dz * dz + dw * dw;
    #pragma unroll
    for (int o = 16; o > 0; o >>= 1) s2 += __shfl_xor_sync(~0u, s2, o);
    if ((tid & 31) == 0) red2[tid >> 5] = s2;
    __syncthreads();
    float inv = rsqrtf((red2[0] + red2[1] + red2[2] + red2[3]) * (1.0f / FDIM) + 1e-3f);
    float4 g = reinterpret_cast<const float4*>(gamma)[tid];
    float4 b = reinterpret_cast<const float4*>(beta)[tid];
    float4 o4 = { dx * inv * g.x + b.x, dy * inv * g.y + b.y,
                  dz * inv * g.z + b.z, dw * inv * g.w + b.w };
    reinterpret_cast<float4*>(g_xn + (size_t)row * FDIM)[tid] = o4;
}

// ---------------------------------------------------------------------------
// Kernel 2: build g_btf in m16n8k8 B-fragment order, tf32-rounded.
// Layout: [ntG 64][ksG 512][lane 32][2]; value(lane,h) = Bmat[k][n] with
// n = ntG*8 + (lane>>2), k = ksG*8 + (lane&3) + 4h; k = f*8+m.
// Thread handles one (f, n), writes m = 0..7.
// ---------------------------------------------------------------------------
__global__ __launch_bounds__(256) void btf_kernel(const float* __restrict__ Wb,
                                                  const float* __restrict__ Ws) {
    int bid = blockIdx.x, t = threadIdx.x;
    int f = bid >> 1;
    int n = ((bid & 1) << 8) + t;
    float w[8];
    w[0] = to_tf32(Wb[(size_t)f * UDIM + n]);
    #pragma unroll
    for (int m = 1; m <= 6; ++m)
        w[m] = to_tf32(Ws[(size_t)(f * 6 + m - 1) * UDIM + n]);
    w[7] = 0.0f;
    size_t base = ((size_t)(n >> 3) * 512 + f) * 64;   // floats
    #pragma unroll
    for (int m = 0; m < 8; ++m) {
        int lane = ((n & 7) << 2) + (m & 3);
        g_btf[base + lane * 2 + (m >> 2)] = w[m];
    }
}

// ---------------------------------------------------------------------------
// closed-form cubic B-spline: 8 packed values (relu, b3[0..5], 0), tf32
// ---------------------------------------------------------------------------
__device__ __forceinline__ void gen8(float xv, float t0, float inv_h, float* v) {
    float xr = (xv - t0) * inv_h;
    float fi = floorf(xr);
    int   i  = (int)fi;
    float s  = xr - fi;
    float s2 = s * s, s3 = s2 * s;
    float u  = 1.0f - s;
    const float c6 = 1.0f / 6.0f;
    float B0 = to_tf32(c6 * u * u * u);
    float B1 = to_tf32(c6 * (3.0f * s3 - 6.0f * s2 + 4.0f));
    float B2 = to_tf32(c6 * (-3.0f * s3 + 3.0f * s2 + 3.0f * s + 1.0f));
    float B3 = to_tf32(c6 * s3);
    bool valid = (xr >= 0.0f) && (i <= 8);
    v[0] = to_tf32(fmaxf(xv, 0.0f));
    #pragma unroll
    for (int j = 0; j < 6; ++j) {
        int d = i - j;
        float bv = (d == 3) ? B0 : (d == 2) ? B1 : (d == 1) ? B2 : (d == 0) ? B3 : 0.0f;
        v[1 + j] = valid ? bv : 0.0f;
    }
    v[7] = 0.0f;
}

// ---------------------------------------------------------------------------
// Kernel 3: fused basis-gen + mma.sync TF32 GEMM.
// Block 256 thr = 8 warps (2 m x 4 n), tile 128x128, K-chunks of 32.
// ---------------------------------------------------------------------------
__global__ __launch_bounds__(256, 2) void kan_mma_kernel(
    const float* __restrict__ grid_knots,   // [10]
    const float* __restrict__ bias,         // [U]
    float* __restrict__ out)                // [N, U]
{
    // A frags: [mt 8][ks 4][slot 32][4 words]; B: [nt 16][ks 4][lane 32][2]
    __shared__ float sA[8 * 4 * 32 * 4];    // 16 KB
    __shared__ float sB[16 * 4 * 32 * 2];   // 16 KB

    const int tid  = threadIdx.x;
    const int lane = tid & 31;
    const int wid  = tid >> 5;
    const int wm   = wid >> 2;              // 0..1
    const int wn   = wid & 3;               // 0..3
    const int row0 = blockIdx.y * 128;
    const int col0 = blockIdx.x * 128;

    const float t0    = __ldg(grid_knots);
    const float inv_h = 1.0f / (__ldg(grid_knots + 1) - t0);

    // acc init = bias (c0,c1 at cols 2t,2t+1; c2,c3 same cols, rows +8)
    float acc[4][4][4];
    #pragma unroll
    for (int in = 0; in < 4; ++in) {
        float2 bb = *reinterpret_cast<const float2*>(
            bias + col0 + wn * 32 + in * 8 + (lane & 3) * 2);
        #pragma unroll
        for (int im = 0; im < 4; ++im) {
            acc[im][in][0] = bb.x; acc[im][in][1] = bb.y;
            acc[im][in][2] = bb.x; acc[im][in][3] = bb.y;
        }
    }

    // gen coords: row gr, feature-half gh (feats 2*gh, 2*gh+1 of each chunk)
    const int gr = tid >> 1;
    const int gh = tid & 1;
    const float* xrow = g_xn + (size_t)(row0 + gr) * FDIM + gh * 2;

    // B copy coords: 16 threads per ntL, 1 KB contiguous per (ntL, chunk)
    const int ntL = tid >> 4;
    const int q   = tid & 15;
    const float4* bsrc = reinterpret_cast<const float4*>(
        g_btf + (size_t)(blockIdx.x * 16 + ntL) * 32768);
    float4* bdst = reinterpret_cast<float4*>(sB) + ntL * 64;

    // prefetch chunk 0
    float4 bq[4];
    #pragma unroll
    for (int i = 0; i < 4; ++i) bq[i] = __ldg(bsrc + q + 16 * i);
    float2 xv = __ldg(reinterpret_cast<const float2*>(xrow));

    const int mtg   = gr >> 4;
    const int r7    = gr & 7;
    const int rhi8  = (gr >> 3) & 1;      // hi-word select within slot

    for (int c = 0; c < NCHUNK; ++c) {
        // generate basis for both features (overlaps other warps' mma tail)
        float v0[8], v1[8];
        gen8(xv.x, t0, inv_h, v0);
        gen8(xv.y, t0, inv_h, v1);

        __syncthreads();   // buffer free (all warps done with mma of c-1)

        // ---- STS A fragments (swizzled slots, STS.64 pairs (kk, kk+4)) ----
        #pragma unroll
        for (int p = 0; p < 2; ++p) {
            const float* vv = p ? v1 : v0;
            int ks = gh * 2 + p;
            char* abase = reinterpret_cast<char*>(sA) + (mtg * 4 + ks) * 512;
            #pragma unroll
            for (int cc = 0; cc < 4; ++cc) {
                int slot = (cc << 3) | (r7 ^ (cc << 1));
                *reinterpret_cast<float2*>(abase + slot * 16 + rhi8 * 8)
                    = make_float2(vv[cc], vv[cc + 4]);
            }
        }
        // ---- STS B (linear copy) ----
        #pragma unroll
        for (int i = 0; i < 4; ++i) bdst[q + 16 * i] = bq[i];

        __syncthreads();   // data ready

        // prefetch next chunk (latency hidden behind mma)
        if (c + 1 < NCHUNK) {
            #pragma unroll
            for (int i = 0; i < 4; ++i)
                bq[i] = __ldg(bsrc + (size_t)(c + 1) * 64 + q + 16 * i);
            xv = __ldg(reinterpret_cast<const float2*>(xrow + (c + 1) * 4));
        }

        // ---- mma phase ----
        const int rslot = ((lane & 3) << 3) | ((lane >> 2) ^ ((lane & 3) << 1));
        #pragma unroll
        for (int ks = 0; ks < 4; ++ks) {
            uint4 a[4];
            #pragma unroll
            for (int im = 0; im < 4; ++im)
                a[im] = *reinterpret_cast<const uint4*>(
                    reinterpret_cast<const char*>(sA) +
                    ((wm * 4 + im) * 4 + ks) * 512 + rslot * 16);
            uint2 b[4];
            #pragma unroll
            for (int in = 0; in < 4; ++in)
                b[in] = *reinterpret_cast<const uint2*>(
                    reinterpret_cast<const char*>(sB) +
                    (((wn * 4 + in) * 4 + ks) * 32 + lane) * 8);
            #pragma unroll
            for (int im = 0; im < 4; ++im)
                #pragma unroll
                for (int in = 0; in < 4; ++in) {
                    // word order in slot: {a0, a2, a1, a3} -> mma {x, z, y, w}
                    asm volatile(
                        "mma.sync.aligned.m16n8k8.row.col.f32.tf32.tf32.f32 "
                        "{%0,%1,%2,%3}, {%4,%5,%6,%7}, {%8,%9}, {%0,%1,%2,%3};"
                        : "+f"(acc[im][in][0]), "+f"(acc[im][in][1]),
                          "+f"(acc[im][in][2]), "+f"(acc[im][in][3])
                        : "r"(a[im].x), "r"(a[im].z), "r"(a[im].y), "r"(a[im].w),
                          "r"(b[in].x), "r"(b[in].y));
                }
        }
    }

    // ---- epilogue ----
    const int g  = lane >> 2;
    const int tq = lane & 3;
    #pragma unroll
    for (int im = 0; im < 4; ++im) {
        int row = row0 + wm * 64 + im * 16 + g;
        #pragma unroll
        for (int in = 0; in < 4; ++in) {
            int col = col0 + wn * 32 + in * 8 + tq * 2;
            *reinterpret_cast<float2*>(out + (size_t)row * UDIM + col)
                = make_float2(acc[im][in][0], acc[im][in][1]);
            *reinterpret_cast<float2*>(out + (size_t)(row + 8) * UDIM + col)
                = make_float2(acc[im][in][2], acc[im][in][3]);
        }
    }
}

// ---------------------------------------------------------------------------
extern "C" void kernel_launch(void* const* d_in, const int* in_sizes, int n_in,
                              void* d_out, int out_size) {
    const float* x     = (const float*)d_in[0];
    const float* gamma = (const float*)d_in[1];
    const float* beta  = (const float*)d_in[2];
    const float* Wb    = (const float*)d_in[3];
    const float* bias  = (const float*)d_in[4];
    const float* Ws    = (const float*)d_in[5];
    const float* grid  = (const float*)d_in[6];
    float* out = (float*)d_out;

    ln_kernel<<<NROWS, 128>>>(x, gamma, beta);
    btf_kernel<<<1024, 256>>>(Wb, Ws);
    kan_mma_kernel<<<dim3(UDIM / 128, NROWS / 128), 256>>>(grid, bias, out);
}

// round 6
// speedup vs baseline: 3.2475x; 1.4476x over previous
#include <cuda_runtime.h>
#include <cuda_fp16.h>
#include <cstdint>

// KANLinear, round 6: fp16 mma.sync m16n8k16, double-buffered single-sync
// pipeline. Fused GEMM: A[32768,4096] (relu + 6 cubic basis + pad0 per
// feature, generated on the fly in fp16 fragment order) @ B^T, with B
// pre-fragmented fp16 in gmem. fp16 mantissa == tf32 mantissa (11 bits), so
// rel_err stays ~3e-4 while mma count and smem bytes halve vs round 5.

#define NROWS 32768
#define FDIM  512
#define UDIM  512
#define NCHUNK 128          // chunks of K=32 (4 features)

__device__ float  g_xn [(size_t)NROWS * FDIM];           // 64 MB LN output
__device__ __half g_btf[(size_t)64 * 256 * 32 * 4];      // 4 MB frag-ordered B

// slot swizzle: 16B-block permutation, octet-distinct mod 8 (conflict-free
// LDS.128) and bank-spread STS.32 (validated in round 5)
#define SIG(L) ((((L) & 3) << 3) | (((L) >> 2) ^ ((((L) & 3) << 1) & 7)))

// ---------------------------------------------------------------------------
// Kernel 1: LayerNorm (identical to passing rounds)
// ---------------------------------------------------------------------------
__global__ __launch_bounds__(128) void ln_kernel(const float* __restrict__ x,
                                                 const float* __restrict__ gamma,
                                                 const float* __restrict__ beta) {
    int row = blockIdx.x, tid = threadIdx.x;
    const float4* xr = reinterpret_cast<const float4*>(x + (size_t)row * FDIM);
    float4 v = xr[tid];
    __shared__ float red[4], red2[4];
    float s = v.x + v.y + v.z + v.w;
    #pragma unroll
    for (int o = 16; o > 0; o >>= 1) s += __shfl_xor_sync(~0u, s, o);
    if ((tid & 31) == 0) red[tid >> 5] = s;
    __syncthreads();
    float mean = (red[0] + red[1] + red[2] + red[3]) * (1.0f / FDIM);
    float dx = v.x - mean, dy = v.y - mean, dz = v.z - mean, dw = v.w - mean;
    float s2 = dx * dx + dy * dy + dz * dz + dw * dw;
    #pragma unroll
    for (int o = 16; o > 0; o >>= 1) s2 += __shfl_xor_sync(~0u, s2, o);
    if ((tid & 31) == 0) red2[tid >> 5] = s2;
    __syncthreads();
    float inv = rsqrtf((red2[0] + red2[1] + red2[2] + red2[3]) * (1.0f / FDIM) + 1e-3f);
    float4 g = reinterpret_cast<const float4*>(gamma)[tid];
    float4 b = reinterpret_cast<const float4*>(beta)[tid];
    float4 o4 = { dx * inv * g.x + b.x, dy * inv * g.y + b.y,
                  dz * inv * g.z + b.z, dw * inv * g.w + b.w };
    reinterpret_cast<float4*>(g_xn + (size_t)row * FDIM)[tid] = o4;
}

// ---------------------------------------------------------------------------
// Kernel 2: build g_btf in m16n8k16 B-fragment order, fp16.
// Layout: [ntG 64][kstepG 256][lane 32][4 halves (b0.lo,b0.hi,b1.lo,b1.hi)]
// value(lane=(n&7)*4+t, reg r, h) = Bmat[k][n], k = kstepG*16 + r*8 + 2t + h,
// k = f*8+m  ->  kstepG = f>>1, r = f&1, 2t+h = m.
// ---------------------------------------------------------------------------
__global__ __launch_bounds__(256) void btf_kernel(const float* __restrict__ Wb,
                                                  const float* __restrict__ Ws) {
    int bid = blockIdx.x, t = threadIdx.x;
    int f = bid >> 1;
    int n = ((bid & 1) << 8) + t;
    float w[8];
    w[0] = Wb[(size_t)f * UDIM + n];
    #pragma unroll
    for (int m = 1; m <= 6; ++m)
        w[m] = Ws[(size_t)(f * 6 + m - 1) * UDIM + n];
    w[7] = 0.0f;
    __half2* dst = reinterpret_cast<__half2*>(g_btf);
    size_t s = ((size_t)(n >> 3) * 256 + (f >> 1)) * 32 + (n & 7) * 4;
    #pragma unroll
    for (int mp = 0; mp < 4; ++mp)
        dst[(s + mp) * 2 + (f & 1)] = __floats2half2_rn(w[2 * mp], w[2 * mp + 1]);
}

// ---------------------------------------------------------------------------
// closed-form cubic B-spline: 8 values (relu, b3[0..5], 0)
// ---------------------------------------------------------------------------
__device__ __forceinline__ void gen8(float xv, float t0, float inv_h, float* v) {
    float xr = (xv - t0) * inv_h;
    float fi = floorf(xr);
    int   i  = (int)fi;
    float s  = xr - fi;
    float s2 = s * s, s3 = s2 * s;
    float u  = 1.0f - s;
    const float c6 = 1.0f / 6.0f;
    float B0 = c6 * u * u * u;
    float B1 = c6 * (3.0f * s3 - 6.0f * s2 + 4.0f);
    float B2 = c6 * (-3.0f * s3 + 3.0f * s2 + 3.0f * s + 1.0f);
    float B3 = c6 * s3;
    bool valid = (xr >= 0.0f) && (i <= 8);
    v[0] = fmaxf(xv, 0.0f);
    #pragma unroll
    for (int j = 0; j < 6; ++j) {
        int d = i - j;
        float bv = (d == 3) ? B0 : (d == 2) ? B1 : (d == 1) ? B2 : (d == 0) ? B3 : 0.0f;
        v[1 + j] = valid ? bv : 0.0f;
    }
    v[7] = 0.0f;
}

// ---------------------------------------------------------------------------
// Kernel 3: fused basis-gen + fp16 mma.sync GEMM, double-buffered.
// Block 256 thr = 8 warps (2 m x 4 n), tile 128x128, K-chunks of 32.
// A frag smem: [stage 2][mt 8][kstep 2][slot 32][16B]; B: [stage 2][nt 16][kstep 2][lane 32][8B]
// ---------------------------------------------------------------------------
__global__ __launch_bounds__(256, 2) void kan_mma_kernel(
    const float* __restrict__ grid_knots,   // [10]
    const float* __restrict__ bias,         // [U]
    float* __restrict__ out)                // [N, U]
{
    __shared__ __align__(16) char sA[2][8192];
    __shared__ __align__(16) char sB[2][8192];

    const int tid  = threadIdx.x;
    const int lane = tid & 31;
    const int wid  = tid >> 5;
    const int wm   = wid >> 2;              // 0..1
    const int wn   = wid & 3;               // 0..3
    const int row0 = blockIdx.y * 128;
    const int col0 = blockIdx.x * 128;

    const float t0    = __ldg(grid_knots);
    const float inv_h = 1.0f / (__ldg(grid_knots + 1) - t0);

    // acc init = bias
    float acc[4][4][4];
    #pragma unroll
    for (int in = 0; in < 4; ++in) {
        float2 bb = *reinterpret_cast<const float2*>(
            bias + col0 + wn * 32 + in * 8 + (lane & 3) * 2);
        #pragma unroll
        for (int im = 0; im < 4; ++im) {
            acc[im][in][0] = bb.x; acc[im][in][1] = bb.y;
            acc[im][in][2] = bb.x; acc[im][in][3] = bb.y;
        }
    }

    // A-gen coords: row gr, kstep gh (features 2gh, 2gh+1 of each 4-feat chunk)
    const int gr = tid >> 1;
    const int gh = tid & 1;
    const float* xrow = g_xn + (size_t)(row0 + gr) * FDIM + gh * 2;
    const int mt  = gr >> 4;
    const int g7  = gr & 7;
    const int hi  = (gr >> 3) & 1;

    // B copy coords
    const int ntL = tid >> 4;
    const int q   = tid & 15;
    const uint4* bsrc = reinterpret_cast<const uint4*>(g_btf) +
                        (size_t)(blockIdx.x * 16 + ntL) * 4096;

    const int rslot = SIG(lane);

    // ---- helpers as lambdas ----
    auto gen_sts = [&](int buf, float2 xv) {
        float vE[8], vO[8];
        gen8(xv.x, t0, inv_h, vE);
        gen8(xv.y, t0, inv_h, vO);
        char* ab = sA[buf] + (mt * 2 + gh) * 512;
        #pragma unroll
        for (int t = 0; t < 4; ++t) {
            int L = g7 * 4 + t;
            int off = SIG(L) * 16 + hi * 4;
            *reinterpret_cast<__half2*>(ab + off) =
                __floats2half2_rn(vE[2 * t], vE[2 * t + 1]);
            *reinterpret_cast<__half2*>(ab + off + 8) =
                __floats2half2_rn(vO[2 * t], vO[2 * t + 1]);
        }
    };

    // prologue: chunk 0 -> buf 0
    {
        float2 xv = __ldg(reinterpret_cast<const float2*>(xrow));
        gen_sts(0, xv);
        uint4* bd = reinterpret_cast<uint4*>(sB[0]) + ntL * 32 + q * 2;
        bd[0] = __ldg(bsrc + q * 2);
        bd[1] = __ldg(bsrc + q * 2 + 1);
    }
    // prefetch chunk 1
    float2 xvp = __ldg(reinterpret_cast<const float2*>(xrow + 4));
    uint4 bq0 = __ldg(bsrc + 32 + q * 2);
    uint4 bq1 = __ldg(bsrc + 32 + q * 2 + 1);

    __syncthreads();

    for (int c = 0; c < NCHUNK; ++c) {
        const int cur = c & 1;

        // fill next buffer (overlaps this chunk's mma on other pipes)
        if (c + 1 < NCHUNK) {
            gen_sts(cur ^ 1, xvp);
            uint4* bd = reinterpret_cast<uint4*>(sB[cur ^ 1]) + ntL * 32 + q * 2;
            bd[0] = bq0;
            bd[1] = bq1;
            if (c + 2 < NCHUNK) {
                xvp = __ldg(reinterpret_cast<const float2*>(xrow + (c + 2) * 4));
                bq0 = __ldg(bsrc + (size_t)(c + 2) * 32 + q * 2);
                bq1 = __ldg(bsrc + (size_t)(c + 2) * 32 + q * 2 + 1);
            }
        }

        // ---- mma on current buffer ----
        #pragma unroll
        for (int ks = 0; ks < 2; ++ks) {
            uint4 a[4];
            #pragma unroll
            for (int im = 0; im < 4; ++im)
                a[im] = *reinterpret_cast<const uint4*>(
                    sA[cur] + ((wm * 4 + im) * 2 + ks) * 512 + rslot * 16);
            uint2 b[4];
            #pragma unroll
            for (int in = 0; in < 4; ++in)
                b[in] = *reinterpret_cast<const uint2*>(
                    sB[cur] + (((wn * 4 + in) * 2 + ks) * 32 + lane) * 8);
            #pragma unroll
            for (int im = 0; im < 4; ++im)
                #pragma unroll
                for (int in = 0; in < 4; ++in) {
                    asm volatile(
                        "mma.sync.aligned.m16n8k16.row.col.f32.f16.f16.f32 "
                        "{%0,%1,%2,%3}, {%4,%5,%6,%7}, {%8,%9}, {%0,%1,%2,%3};"
                        : "+f"(acc[im][in][0]), "+f"(acc[im][in][1]),
                          "+f"(acc[im][in][2]), "+f"(acc[im][in][3])
                        : "r"(a[im].x), "r"(a[im].y), "r"(a[im].z), "r"(a[im].w),
                          "r"(b[in].x), "r"(b[in].y));
                }
        }

        __syncthreads();
    }

    // ---- epilogue ----
    const int g  = lane >> 2;
    const int tq = lane & 3;
    #pragma unroll
    for (int im = 0; im < 4; ++im) {
        int row = row0 + wm * 64 + im * 16 + g;
        #pragma unroll
        for (int in = 0; in < 4; ++in) {
            int col = col0 + wn * 32 + in * 8 + tq * 2;
            *reinterpret_cast<float2*>(out + (size_t)row * UDIM + col)
                = make_float2(acc[im][in][0], acc[im][in][1]);
            *reinterpret_cast<float2*>(out + (size_t)(row + 8) * UDIM + col)
                = make_float2(acc[im][in][2], acc[im][in][3]);
        }
    }
}

// ---------------------------------------------------------------------------
extern "C" void kernel_launch(void* const* d_in, const int* in_sizes, int n_in,
                              void* d_out, int out_size) {
    const float* x     = (const float*)d_in[0];
    const float* gamma = (const float*)d_in[1];
    const float* beta  = (const float*)d_in[2];
    const float* Wb    = (const float*)d_in[3];
    const float* bias  = (const float*)d_in[4];
    const float* Ws    = (const float*)d_in[5];
    const float* grid  = (const float*)d_in[6];
    float* out = (float*)d_out;

    ln_kernel<<<NROWS, 128>>>(x, gamma, beta);
    btf_kernel<<<1024, 256>>>(Wb, Ws);
    kan_mma_kernel<<<dim3(UDIM / 128, NROWS / 128), 256>>>(grid, bias, out);
}

// round 7
// speedup vs baseline: 4.7859x; 1.4737x over previous
#include <cuda_runtime.h>
#include <cuda_fp16.h>
#include <cstdint>

// KANLinear, round 7: precomputed fragment-ordered A in gmem + pure
// LDG->HMMA GEMM (no smem, no __syncthreads in the GEMM).
// Pipeline: ln_kernel -> btf_kernel (B frags, 1x) -> af_kernel (A frags, 1x)
//           -> kan_mma_kernel (fp16 m16n8k16, fp32 acc).

#define NROWS 32768
#define FDIM  512
#define UDIM  512
#define NCHUNK 128           // 32-k chunks
#define NKSTEP 256           // 16-k steps

__device__ float  g_xn [(size_t)NROWS * FDIM];            // 64 MB LN output
__device__ __half g_btf[(size_t)64 * NKSTEP * 32 * 4];    // 4 MB B frags
__device__ __half g_af [(size_t)2048 * NKSTEP * 32 * 8];  // 256 MB A frags

// slot permutation (validated round 5/6): conflict-free frag access
#define SIG(L) ((((L) & 3) << 3) | (((L) >> 2) ^ ((((L) & 3) << 1) & 7)))

// ---------------------------------------------------------------------------
// Kernel 1: LayerNorm (unchanged, passing)
// ---------------------------------------------------------------------------
__global__ __launch_bounds__(128) void ln_kernel(const float* __restrict__ x,
                                                 const float* __restrict__ gamma,
                                                 const float* __restrict__ beta) {
    int row = blockIdx.x, tid = threadIdx.x;
    const float4* xr = reinterpret_cast<const float4*>(x + (size_t)row * FDIM);
    float4 v = xr[tid];
    __shared__ float red[4], red2[4];
    float s = v.x + v.y + v.z + v.w;
    #pragma unroll
    for (int o = 16; o > 0; o >>= 1) s += __shfl_xor_sync(~0u, s, o);
    if ((tid & 31) == 0) red[tid >> 5] = s;
    __syncthreads();
    float mean = (red[0] + red[1] + red[2] + red[3]) * (1.0f / FDIM);
    float dx = v.x - mean, dy = v.y - mean, dz = v.z - mean, dw = v.w - mean;
    float s2 = dx * dx + dy * dy + dz * dz + dw * dw;
    #pragma unroll
    for (int o = 16; o > 0; o >>= 1) s2 += __shfl_xor_sync(~0u, s2, o);
    if ((tid & 31) == 0) red2[tid >> 5] = s2;
    __syncthreads();
    float inv = rsqrtf((red2[0] + red2[1] + red2[2] + red2[3]) * (1.0f / FDIM) + 1e-3f);
    float4 g = reinterpret_cast<const float4*>(gamma)[tid];
    float4 b = reinterpret_cast<const float4*>(beta)[tid];
    float4 o4 = { dx * inv * g.x + b.x, dy * inv * g.y + b.y,
                  dz * inv * g.z + b.z, dw * inv * g.w + b.w };
    reinterpret_cast<float4*>(g_xn + (size_t)row * FDIM)[tid] = o4;
}

// ---------------------------------------------------------------------------
// Kernel 2: B fragments (byte-identical to round 6, passing)
// ---------------------------------------------------------------------------
__global__ __launch_bounds__(256) void btf_kernel(const float* __restrict__ Wb,
                                                  const float* __restrict__ Ws) {
    int bid = blockIdx.x, t = threadIdx.x;
    int f = bid >> 1;
    int n = ((bid & 1) << 8) + t;
    float w[8];
    w[0] = Wb[(size_t)f * UDIM + n];
    #pragma unroll
    for (int m = 1; m <= 6; ++m)
        w[m] = Ws[(size_t)(f * 6 + m - 1) * UDIM + n];
    w[7] = 0.0f;
    __half2* dst = reinterpret_cast<__half2*>(g_btf);
    size_t s = ((size_t)(n >> 3) * 256 + (f >> 1)) * 32 + (n & 7) * 4;
    #pragma unroll
    for (int mp = 0; mp < 4; ++mp)
        dst[(s + mp) * 2 + (f & 1)] = __floats2half2_rn(w[2 * mp], w[2 * mp + 1]);
}

// ---------------------------------------------------------------------------
// closed-form cubic B-spline (unchanged, passing)
// ---------------------------------------------------------------------------
__device__ __forceinline__ void gen8(float xv, float t0, float inv_h, float* v) {
    float xr = (xv - t0) * inv_h;
    float fi = floorf(xr);
    int   i  = (int)fi;
    float s  = xr - fi;
    float s2 = s * s, s3 = s2 * s;
    float u  = 1.0f - s;
    const float c6 = 1.0f / 6.0f;
    float B0 = c6 * u * u * u;
    float B1 = c6 * (3.0f * s3 - 6.0f * s2 + 4.0f);
    float B2 = c6 * (-3.0f * s3 + 3.0f * s2 + 3.0f * s + 1.0f);
    float B3 = c6 * s3;
    bool valid = (xr >= 0.0f) && (i <= 8);
    v[0] = fmaxf(xv, 0.0f);
    #pragma unroll
    for (int j = 0; j < 6; ++j) {
        int d = i - j;
        float bv = (d == 3) ? B0 : (d == 2) ? B1 : (d == 1) ? B2 : (d == 0) ? B3 : 0.0f;
        v[1 + j] = valid ? bv : 0.0f;
    }
    v[7] = 0.0f;
}

// ---------------------------------------------------------------------------
// Kernel 3: A fragments -> gmem. Block = 256 thr handles 128 rows.
// smem staging layout per chunk: [mt 8][gh 2][SIG(lane) 32][16B] (round-6
// gen_sts indexing verbatim), then 512B-block copy to
// g_af[(mtG*256 + kstep)*512B].
// ---------------------------------------------------------------------------
__global__ __launch_bounds__(256) void af_kernel(const float* __restrict__ grid_knots) {
    __shared__ __align__(16) char st[8192];
    const int tid = threadIdx.x;
    const float t0    = __ldg(grid_knots);
    const float inv_h = 1.0f / (__ldg(grid_knots + 1) - t0);

    const int gr = tid >> 1;          // 0..127 row within block
    const int gh = tid & 1;           // kstep within chunk
    const float* xrow = g_xn + (size_t)(blockIdx.x * 128 + gr) * FDIM + gh * 2;
    const int mt = gr >> 4;
    const int g7 = gr & 7;
    const int hi = (gr >> 3) & 1;

    // copy-out coords: thread -> (mtc, ghc), 32B each
    const int mtc = tid >> 5;         // (tid>>4)>>1
    const int ghc = (tid >> 4) & 1;
    const int qo  = (tid & 15) * 2;   // uint4 offset within 512B
    const size_t mtG0 = (size_t)blockIdx.x * 8;

    for (int c = 0; c < NCHUNK; ++c) {
        float2 xv = __ldg(reinterpret_cast<const float2*>(xrow + c * 4));
        float vE[8], vO[8];
        gen8(xv.x, t0, inv_h, vE);
        gen8(xv.y, t0, inv_h, vO);
        char* ab = st + (mt * 2 + gh) * 512;
        #pragma unroll
        for (int t = 0; t < 4; ++t) {
            int L = g7 * 4 + t;
            int off = SIG(L) * 16 + hi * 4;
            *reinterpret_cast<__half2*>(ab + off) =
                __floats2half2_rn(vE[2 * t], vE[2 * t + 1]);
            *reinterpret_cast<__half2*>(ab + off + 8) =
                __floats2half2_rn(vO[2 * t], vO[2 * t + 1]);
        }
        __syncthreads();
        {
            const uint4* src = reinterpret_cast<const uint4*>(
                st + (mtc * 2 + ghc) * 512) + qo;
            uint4* dst = reinterpret_cast<uint4*>(g_af) +
                ((mtG0 + mtc) * NKSTEP + (c * 2 + ghc)) * 32 + qo;
            dst[0] = src[0];
            dst[1] = src[1];
        }
        __syncthreads();
    }
}

// ---------------------------------------------------------------------------
// Kernel 4: pure LDG->HMMA GEMM. 256 thr = 8 warps (2m x 4n), tile 128x128,
// warp tile 64x32. No smem, no barriers; 2-deep register pipeline.
// ---------------------------------------------------------------------------
__global__ __launch_bounds__(256, 2) void kan_mma_kernel(
    const float* __restrict__ bias, float* __restrict__ out)
{
    const int tid  = threadIdx.x;
    const int lane = tid & 31;
    const int wid  = tid >> 5;
    const int wm   = wid >> 2;
    const int wn   = wid & 3;
    const int row0 = blockIdx.y * 128;
    const int col0 = blockIdx.x * 128;

    // frag base pointers
    const uint4* abase = reinterpret_cast<const uint4*>(g_af) +
        ((size_t)(blockIdx.y * 8 + wm * 4) * NKSTEP) * 32 + SIG(lane);
    const uint2* bbase = reinterpret_cast<const uint2*>(g_btf) +
        ((size_t)(blockIdx.x * 16 + wn * 4) * NKSTEP) * 32 + lane;

    // acc init = bias
    float acc[4][4][4];
    #pragma unroll
    for (int in = 0; in < 4; ++in) {
        float2 bb = *reinterpret_cast<const float2*>(
            bias + col0 + wn * 32 + in * 8 + (lane & 3) * 2);
        #pragma unroll
        for (int im = 0; im < 4; ++im) {
            acc[im][in][0] = bb.x; acc[im][in][1] = bb.y;
            acc[im][in][2] = bb.x; acc[im][in][3] = bb.y;
        }
    }

    uint4 aC[4], aN[4];
    uint2 bC[4], bN[4];
    #pragma unroll
    for (int im = 0; im < 4; ++im) aC[im] = __ldg(abase + (size_t)im * (NKSTEP * 32));
    #pragma unroll
    for (int in = 0; in < 4; ++in) bC[in] = __ldg(bbase + (size_t)in * (NKSTEP * 32));

    for (int ks = 0; ks < NKSTEP; ++ks) {
        if (ks + 1 < NKSTEP) {
            #pragma unroll
            for (int im = 0; im < 4; ++im)
                aN[im] = __ldg(abase + (size_t)im * (NKSTEP * 32) + (ks + 1) * 32);
            #pragma unroll
            for (int in = 0; in < 4; ++in)
                bN[in] = __ldg(bbase + (size_t)in * (NKSTEP * 32) + (ks + 1) * 32);
        }
        #pragma unroll
        for (int im = 0; im < 4; ++im)
            #pragma unroll
            for (int in = 0; in < 4; ++in) {
                asm volatile(
                    "mma.sync.aligned.m16n8k16.row.col.f32.f16.f16.f32 "
                    "{%0,%1,%2,%3}, {%4,%5,%6,%7}, {%8,%9}, {%0,%1,%2,%3};"
                    : "+f"(acc[im][in][0]), "+f"(acc[im][in][1]),
                      "+f"(acc[im][in][2]), "+f"(acc[im][in][3])
                    : "r"(aC[im].x), "r"(aC[im].y), "r"(aC[im].z), "r"(aC[im].w),
                      "r"(bC[in].x), "r"(bC[in].y));
            }
        #pragma unroll
        for (int im = 0; im < 4; ++im) aC[im] = aN[im];
        #pragma unroll
        for (int in = 0; in < 4; ++in) bC[in] = bN[in];
    }

    // epilogue (round-6 mapping, passing)
    const int g  = lane >> 2;
    const int tq = lane & 3;
    #pragma unroll
    for (int im = 0; im < 4; ++im) {
        int row = row0 + wm * 64 + im * 16 + g;
        #pragma unroll
        for (int in = 0; in < 4; ++in) {
            int col = col0 + wn * 32 + in * 8 + tq * 2;
            *reinterpret_cast<float2*>(out + (size_t)row * UDIM + col)
                = make_float2(acc[im][in][0], acc[im][in][1]);
            *reinterpret_cast<float2*>(out + (size_t)(row + 8) * UDIM + col)
                = make_float2(acc[im][in][2], acc[im][in][3]);
        }
    }
}

// ---------------------------------------------------------------------------
extern "C" void kernel_launch(void* const* d_in, const int* in_sizes, int n_in,
                              void* d_out, int out_size) {
    const float* x     = (const float*)d_in[0];
    const float* gamma = (const float*)d_in[1];
    const float* beta  = (const float*)d_in[2];
    const float* Wb    = (const float*)d_in[3];
    const float* bias  = (const float*)d_in[4];
    const float* Ws    = (const float*)d_in[5];
    const float* grid  = (const float*)d_in[6];
    float* out = (float*)d_out;

    ln_kernel<<<NROWS, 128>>>(x, gamma, beta);
    btf_kernel<<<1024, 256>>>(Wb, Ws);
    af_kernel<<<NROWS / 128, 256>>>(grid);
    kan_mma_kernel<<<dim3(UDIM / 128, NROWS / 128), 256>>>(bias, out);
}

// round 8
// speedup vs baseline: 5.8545x; 1.2233x over previous
#include <cuda_runtime.h>
#include <cuda_fp16.h>
#include <cstdint>

// KANLinear, round 8: same as round 7 except af_kernel is parallelized
// (grid 256 -> 2048 via chunk-split) and double-buffered (1 barrier/chunk).
// Pipeline: ln -> btf (B frags) -> af (A frags) -> pure LDG->HMMA GEMM.

#define NROWS 32768
#define FDIM  512
#define UDIM  512
#define NCHUNK 128           // 32-k chunks
#define NKSTEP 256           // 16-k steps
#define AF_CG  8             // chunk-groups per row-block
#define AF_CPB (NCHUNK / AF_CG)   // 16 chunks per af block

__device__ float  g_xn [(size_t)NROWS * FDIM];            // 64 MB LN output
__device__ __half g_btf[(size_t)64 * NKSTEP * 32 * 4];    // 4 MB B frags
__device__ __half g_af [(size_t)2048 * NKSTEP * 32 * 8];  // 256 MB A frags

// slot permutation (validated rounds 5-7)
#define SIG(L) ((((L) & 3) << 3) | (((L) >> 2) ^ ((((L) & 3) << 1) & 7)))

// ---------------------------------------------------------------------------
// Kernel 1: LayerNorm (unchanged, passing)
// ---------------------------------------------------------------------------
__global__ __launch_bounds__(128) void ln_kernel(const float* __restrict__ x,
                                                 const float* __restrict__ gamma,
                                                 const float* __restrict__ beta) {
    int row = blockIdx.x, tid = threadIdx.x;
    const float4* xr = reinterpret_cast<const float4*>(x + (size_t)row * FDIM);
    float4 v = xr[tid];
    __shared__ float red[4], red2[4];
    float s = v.x + v.y + v.z + v.w;
    #pragma unroll
    for (int o = 16; o > 0; o >>= 1) s += __shfl_xor_sync(~0u, s, o);
    if ((tid & 31) == 0) red[tid >> 5] = s;
    __syncthreads();
    float mean = (red[0] + red[1] + red[2] + red[3]) * (1.0f / FDIM);
    float dx = v.x - mean, dy = v.y - mean, dz = v.z - mean, dw = v.w - mean;
    float s2 = dx * dx + dy * dy + dz * dz + dw * dw;
    #pragma unroll
    for (int o = 16; o > 0; o >>= 1) s2 += __shfl_xor_sync(~0u, s2, o);
    if ((tid & 31) == 0) red2[tid >> 5] = s2;
    __syncthreads();
    float inv = rsqrtf((red2[0] + red2[1] + red2[2] + red2[3]) * (1.0f / FDIM) + 1e-3f);
    float4 g = reinterpret_cast<const float4*>(gamma)[tid];
    float4 b = reinterpret_cast<const float4*>(beta)[tid];
    float4 o4 = { dx * inv * g.x + b.x, dy * inv * g.y + b.y,
                  dz * inv * g.z + b.z, dw * inv * g.w + b.w };
    reinterpret_cast<float4*>(g_xn + (size_t)row * FDIM)[tid] = o4;
}

// ---------------------------------------------------------------------------
// Kernel 2: B fragments (byte-identical to rounds 6-7, passing)
// ---------------------------------------------------------------------------
__global__ __launch_bounds__(256) void btf_kernel(const float* __restrict__ Wb,
                                                  const float* __restrict__ Ws) {
    int bid = blockIdx.x, t = threadIdx.x;
    int f = bid >> 1;
    int n = ((bid & 1) << 8) + t;
    float w[8];
    w[0] = Wb[(size_t)f * UDIM + n];
    #pragma unroll
    for (int m = 1; m <= 6; ++m)
        w[m] = Ws[(size_t)(f * 6 + m - 1) * UDIM + n];
    w[7] = 0.0f;
    __half2* dst = reinterpret_cast<__half2*>(g_btf);
    size_t s = ((size_t)(n >> 3) * 256 + (f >> 1)) * 32 + (n & 7) * 4;
    #pragma unroll
    for (int mp = 0; mp < 4; ++mp)
        dst[(s + mp) * 2 + (f & 1)] = __floats2half2_rn(w[2 * mp], w[2 * mp + 1]);
}

// ---------------------------------------------------------------------------
// closed-form cubic B-spline (unchanged, passing)
// ---------------------------------------------------------------------------
__device__ __forceinline__ void gen8(float xv, float t0, float inv_h, float* v) {
    float xr = (xv - t0) * inv_h;
    float fi = floorf(xr);
    int   i  = (int)fi;
    float s  = xr - fi;
    float s2 = s * s, s3 = s2 * s;
    float u  = 1.0f - s;
    const float c6 = 1.0f / 6.0f;
    float B0 = c6 * u * u * u;
    float B1 = c6 * (3.0f * s3 - 6.0f * s2 + 4.0f);
    float B2 = c6 * (-3.0f * s3 + 3.0f * s2 + 3.0f * s + 1.0f);
    float B3 = c6 * s3;
    bool valid = (xr >= 0.0f) && (i <= 8);
    v[0] = fmaxf(xv, 0.0f);
    #pragma unroll
    for (int j = 0; j < 6; ++j) {
        int d = i - j;
        float bv = (d == 3) ? B0 : (d == 2) ? B1 : (d == 1) ? B2 : (d == 0) ? B3 : 0.0f;
        v[1 + j] = valid ? bv : 0.0f;
    }
    v[7] = 0.0f;
}

// ---------------------------------------------------------------------------
// Kernel 3: A fragments -> gmem.
// Grid (AF_CG=8 chunk-groups, 256 row-blocks); block = 256 thr, 16 chunks.
// Double-buffered staging: one __syncthreads per chunk.
// Indexing identical to the round-7 passing version, c offset by group.
// ---------------------------------------------------------------------------
__global__ __launch_bounds__(256) void af_kernel(const float* __restrict__ grid_knots) {
    __shared__ __align__(16) char st[2][8192];
    const int tid = threadIdx.x;
    const float t0    = __ldg(grid_knots);
    const float inv_h = 1.0f / (__ldg(grid_knots + 1) - t0);

    const int c0 = blockIdx.x * AF_CPB;          // first chunk of this group
    const int rb = blockIdx.y;                   // row-block

    const int gr = tid >> 1;          // 0..127 row within block
    const int gh = tid & 1;           // kstep within chunk
    const float* xrow = g_xn + (size_t)(rb * 128 + gr) * FDIM + gh * 2;
    const int mt = gr >> 4;
    const int g7 = gr & 7;
    const int hi = (gr >> 3) & 1;

    // copy-out coords: thread -> (mtc, ghc), 32B each
    const int mtc = tid >> 5;
    const int ghc = (tid >> 4) & 1;
    const int qo  = (tid & 15) * 2;   // uint4 offset within 512B
    const size_t mtG0 = (size_t)rb * 8;

    #pragma unroll 1
    for (int cc = 0; cc < AF_CPB; ++cc) {
        const int c   = c0 + cc;
        const int buf = cc & 1;
        float2 xv = __ldg(reinterpret_cast<const float2*>(xrow + c * 4));
        float vE[8], vO[8];
        gen8(xv.x, t0, inv_h, vE);
        gen8(xv.y, t0, inv_h, vO);
        char* ab = st[buf] + (mt * 2 + gh) * 512;
        #pragma unroll
        for (int t = 0; t < 4; ++t) {
            int L = g7 * 4 + t;
            int off = SIG(L) * 16 + hi * 4;
            *reinterpret_cast<__half2*>(ab + off) =
                __floats2half2_rn(vE[2 * t], vE[2 * t + 1]);
            *reinterpret_cast<__half2*>(ab + off + 8) =
                __floats2half2_rn(vO[2 * t], vO[2 * t + 1]);
        }
        __syncthreads();   // staging of this buffer complete (and the copy
                           // issued from this buffer two iterations ago has
                           // been read out before its reuse next iteration)
        {
            const uint4* src = reinterpret_cast<const uint4*>(
                st[buf] + (mtc * 2 + ghc) * 512) + qo;
            uint4* dst = reinterpret_cast<uint4*>(g_af) +
                ((mtG0 + mtc) * NKSTEP + (c * 2 + ghc)) * 32 + qo;
            dst[0] = src[0];
            dst[1] = src[1];
        }
    }
}

// ---------------------------------------------------------------------------
// Kernel 4: pure LDG->HMMA GEMM (byte-identical to round 7, passing).
// ---------------------------------------------------------------------------
__global__ __launch_bounds__(256, 2) void kan_mma_kernel(
    const float* __restrict__ bias, float* __restrict__ out)
{
    const int tid  = threadIdx.x;
    const int lane = tid & 31;
    const int wid  = tid >> 5;
    const int wm   = wid >> 2;
    const int wn   = wid & 3;
    const int row0 = blockIdx.y * 128;
    const int col0 = blockIdx.x * 128;

    const uint4* abase = reinterpret_cast<const uint4*>(g_af) +
        ((size_t)(blockIdx.y * 8 + wm * 4) * NKSTEP) * 32 + SIG(lane);
    const uint2* bbase = reinterpret_cast<const uint2*>(g_btf) +
        ((size_t)(blockIdx.x * 16 + wn * 4) * NKSTEP) * 32 + lane;

    float acc[4][4][4];
    #pragma unroll
    for (int in = 0; in < 4; ++in) {
        float2 bb = *reinterpret_cast<const float2*>(
            bias + col0 + wn * 32 + in * 8 + (lane & 3) * 2);
        #pragma unroll
        for (int im = 0; im < 4; ++im) {
            acc[im][in][0] = bb.x; acc[im][in][1] = bb.y;
            acc[im][in][2] = bb.x; acc[im][in][3] = bb.y;
        }
    }

    uint4 aC[4], aN[4];
    uint2 bC[4], bN[4];
    #pragma unroll
    for (int im = 0; im < 4; ++im) aC[im] = __ldg(abase + (size_t)im * (NKSTEP * 32));
    #pragma unroll
    for (int in = 0; in < 4; ++in) bC[in] = __ldg(bbase + (size_t)in * (NKSTEP * 32));

    for (int ks = 0; ks < NKSTEP; ++ks) {
        if (ks + 1 < NKSTEP) {
            #pragma unroll
            for (int im = 0; im < 4; ++im)
                aN[im] = __ldg(abase + (size_t)im * (NKSTEP * 32) + (ks + 1) * 32);
            #pragma unroll
            for (int in = 0; in < 4; ++in)
                bN[in] = __ldg(bbase + (size_t)in * (NKSTEP * 32) + (ks + 1) * 32);
        }
        #pragma unroll
        for (int im = 0; im < 4; ++im)
            #pragma unroll
            for (int in = 0; in < 4; ++in) {
                asm volatile(
                    "mma.sync.aligned.m16n8k16.row.col.f32.f16.f16.f32 "
                    "{%0,%1,%2,%3}, {%4,%5,%6,%7}, {%8,%9}, {%0,%1,%2,%3};"
                    : "+f"(acc[im][in][0]), "+f"(acc[im][in][1]),
                      "+f"(acc[im][in][2]), "+f"(acc[im][in][3])
                    : "r"(aC[im].x), "r"(aC[im].y), "r"(aC[im].z), "r"(aC[im].w),
                      "r"(bC[in].x), "r"(bC[in].y));
            }
        #pragma unroll
        for (int im = 0; im < 4; ++im) aC[im] = aN[im];
        #pragma unroll
        for (int in = 0; in < 4; ++in) bC[in] = bN[in];
    }

    const int g  = lane >> 2;
    const int tq = lane & 3;
    #pragma unroll
    for (int im = 0; im < 4; ++im) {
        int row = row0 + wm * 64 + im * 16 + g;
        #pragma unroll
        for (int in = 0; in < 4; ++in) {
            int col = col0 + wn * 32 + in * 8 + tq * 2;
            *reinterpret_cast<float2*>(out + (size_t)row * UDIM + col)
                = make_float2(acc[im][in][0], acc[im][in][1]);
            *reinterpret_cast<float2*>(out + (size_t)(row + 8) * UDIM + col)
                = make_float2(acc[im][in][2], acc[im][in][3]);
        }
    }
}

// ---------------------------------------------------------------------------
extern "C" void kernel_launch(void* const* d_in, const int* in_sizes, int n_in,
                              void* d_out, int out_size) {
    const float* x     = (const float*)d_in[0];
    const float* gamma = (const float*)d_in[1];
    const float* beta  = (const float*)d_in[2];
    const float* Wb    = (const float*)d_in[3];
    const float* bias  = (const float*)d_in[4];
    const float* Ws    = (const float*)d_in[5];
    const float* grid  = (const float*)d_in[6];
    float* out = (float*)d_out;

    ln_kernel<<<NROWS, 128>>>(x, gamma, beta);
    btf_kernel<<<1024, 256>>>(Wb, Ws);
    af_kernel<<<dim3(AF_CG, NROWS / 128), 256>>>(grid);
    kan_mma_kernel<<<dim3(UDIM / 128, NROWS / 128), 256>>>(bias, out);
}

// round 9
// speedup vs baseline: 8.1491x; 1.3919x over previous
#include <cuda_runtime.h>
#include <cuda_fp16.h>
#include <cstdint>

// KANLinear, round 9: cp.async 3-stage smem pipeline feeding fp16 m16n8k16
// mma. af/btf/ln identical to round 8 (passing). GEMM: CTA tile 128x128,
// stage = 4 ksteps (A 16KB + B 16KB), frags staged once per CTA.

#define NROWS 32768
#define FDIM  512
#define UDIM  512
#define NCHUNK 128
#define NKSTEP 256
#define AF_CG  8
#define AF_CPB (NCHUNK / AF_CG)

#define BIG    4                    // ksteps per stage
#define NIT    (NKSTEP / BIG)       // 64
#define STG_BYTES 32768             // 16KB A + 16KB B
#define NSTG   3
#define SMEM_TOTAL (NSTG * STG_BYTES)

__device__ float  g_xn [(size_t)NROWS * FDIM];            // 64 MB LN output
__device__ __half g_btf[(size_t)64 * NKSTEP * 32 * 4];    // 4 MB B frags
__device__ __half g_af [(size_t)2048 * NKSTEP * 32 * 8];  // 256 MB A frags

#define SIG(L) ((((L) & 3) << 3) | (((L) >> 2) ^ ((((L) & 3) << 1) & 7)))

__device__ __forceinline__ uint32_t smem_u32(const void* p) {
    uint32_t a;
    asm("{ .reg .u64 t; cvta.to.shared.u64 t, %1; cvt.u32.u64 %0, t; }"
        : "=r"(a) : "l"(p));
    return a;
}
#define CP_ASYNC16(dst_u32, src_ptr) \
    asm volatile("cp.async.cg.shared.global [%0], [%1], 16;" \
                 :: "r"(dst_u32), "l"(src_ptr) : "memory")
#define CP_COMMIT() asm volatile("cp.async.commit_group;" ::: "memory")
#define CP_WAIT1()  asm volatile("cp.async.wait_group 1;" ::: "memory")

// ---------------------------------------------------------------------------
// Kernel 1: LayerNorm (unchanged, passing)
// ---------------------------------------------------------------------------
__global__ __launch_bounds__(128) void ln_kernel(const float* __restrict__ x,
                                                 const float* __restrict__ gamma,
                                                 const float* __restrict__ beta) {
    int row = blockIdx.x, tid = threadIdx.x;
    const float4* xr = reinterpret_cast<const float4*>(x + (size_t)row * FDIM);
    float4 v = xr[tid];
    __shared__ float red[4], red2[4];
    float s = v.x + v.y + v.z + v.w;
    #pragma unroll
    for (int o = 16; o > 0; o >>= 1) s += __shfl_xor_sync(~0u, s, o);
    if ((tid & 31) == 0) red[tid >> 5] = s;
    __syncthreads();
    float mean = (red[0] + red[1] + red[2] + red[3]) * (1.0f / FDIM);
    float dx = v.x - mean, dy = v.y - mean, dz = v.z - mean, dw = v.w - mean;
    float s2 = dx * dx + dy * dy + dz * dz + dw * dw;
    #pragma unroll
    for (int o = 16; o > 0; o >>= 1) s2 += __shfl_xor_sync(~0u, s2, o);
    if ((tid & 31) == 0) red2[tid >> 5] = s2;
    __syncthreads();
    float inv = rsqrtf((red2[0] + red2[1] + red2[2] + red2[3]) * (1.0f / FDIM) + 1e-3f);
    float4 g = reinterpret_cast<const float4*>(gamma)[tid];
    float4 b = reinterpret_cast<const float4*>(beta)[tid];
    float4 o4 = { dx * inv * g.x + b.x, dy * inv * g.y + b.y,
                  dz * inv * g.z + b.z, dw * inv * g.w + b.w };
    reinterpret_cast<float4*>(g_xn + (size_t)row * FDIM)[tid] = o4;
}

// ---------------------------------------------------------------------------
// Kernel 2: B fragments (unchanged, passing)
// ---------------------------------------------------------------------------
__global__ __launch_bounds__(256) void btf_kernel(const float* __restrict__ Wb,
                                                  const float* __restrict__ Ws) {
    int bid = blockIdx.x, t = threadIdx.x;
    int f = bid >> 1;
    int n = ((bid & 1) << 8) + t;
    float w[8];
    w[0] = Wb[(size_t)f * UDIM + n];
    #pragma unroll
    for (int m = 1; m <= 6; ++m)
        w[m] = Ws[(size_t)(f * 6 + m - 1) * UDIM + n];
    w[7] = 0.0f;
    __half2* dst = reinterpret_cast<__half2*>(g_btf);
    size_t s = ((size_t)(n >> 3) * 256 + (f >> 1)) * 32 + (n & 7) * 4;
    #pragma unroll
    for (int mp = 0; mp < 4; ++mp)
        dst[(s + mp) * 2 + (f & 1)] = __floats2half2_rn(w[2 * mp], w[2 * mp + 1]);
}

// ---------------------------------------------------------------------------
// closed-form cubic B-spline (unchanged, passing)
// ---------------------------------------------------------------------------
__device__ __forceinline__ void gen8(float xv, float t0, float inv_h, float* v) {
    float xr = (xv - t0) * inv_h;
    float fi = floorf(xr);
    int   i  = (int)fi;
    float s  = xr - fi;
    float s2 = s * s, s3 = s2 * s;
    float u  = 1.0f - s;
    const float c6 = 1.0f / 6.0f;
    float B0 = c6 * u * u * u;
    float B1 = c6 * (3.0f * s3 - 6.0f * s2 + 4.0f);
    float B2 = c6 * (-3.0f * s3 + 3.0f * s2 + 3.0f * s + 1.0f);
    float B3 = c6 * s3;
    bool valid = (xr >= 0.0f) && (i <= 8);
    v[0] = fmaxf(xv, 0.0f);
    #pragma unroll
    for (int j = 0; j < 6; ++j) {
        int d = i - j;
        float bv = (d == 3) ? B0 : (d == 2) ? B1 : (d == 1) ? B2 : (d == 0) ? B3 : 0.0f;
        v[1 + j] = valid ? bv : 0.0f;
    }
    v[7] = 0.0f;
}

// ---------------------------------------------------------------------------
// Kernel 3: A fragments -> gmem (unchanged from round 8, passing)
// ---------------------------------------------------------------------------
__global__ __launch_bounds__(256) void af_kernel(const float* __restrict__ grid_knots) {
    __shared__ __align__(16) char st[2][8192];
    const int tid = threadIdx.x;
    const float t0    = __ldg(grid_knots);
    const float inv_h = 1.0f / (__ldg(grid_knots + 1) - t0);

    const int c0 = blockIdx.x * AF_CPB;
    const int rb = blockIdx.y;

    const int gr = tid >> 1;
    const int gh = tid & 1;
    const float* xrow = g_xn + (size_t)(rb * 128 + gr) * FDIM + gh * 2;
    const int mt = gr >> 4;
    const int g7 = gr & 7;
    const int hi = (gr >> 3) & 1;

    const int mtc = tid >> 5;
    const int ghc = (tid >> 4) & 1;
    const int qo  = (tid & 15) * 2;
    const size_t mtG0 = (size_t)rb * 8;

    #pragma unroll 1
    for (int cc = 0; cc < AF_CPB; ++cc) {
        const int c   = c0 + cc;
        const int buf = cc & 1;
        float2 xv = __ldg(reinterpret_cast<const float2*>(xrow + c * 4));
        float vE[8], vO[8];
        gen8(xv.x, t0, inv_h, vE);
        gen8(xv.y, t0, inv_h, vO);
        char* ab = st[buf] + (mt * 2 + gh) * 512;
        #pragma unroll
        for (int t = 0; t < 4; ++t) {
            int L = g7 * 4 + t;
            int off = SIG(L) * 16 + hi * 4;
            *reinterpret_cast<__half2*>(ab + off) =
                __floats2half2_rn(vE[2 * t], vE[2 * t + 1]);
            *reinterpret_cast<__half2*>(ab + off + 8) =
                __floats2half2_rn(vO[2 * t], vO[2 * t + 1]);
        }
        __syncthreads();
        {
            const uint4* src = reinterpret_cast<const uint4*>(
                st[buf] + (mtc * 2 + ghc) * 512) + qo;
            uint4* dst = reinterpret_cast<uint4*>(g_af) +
                ((mtG0 + mtc) * NKSTEP + (c * 2 + ghc)) * 32 + qo;
            dst[0] = src[0];
            dst[1] = src[1];
        }
    }
}

// ---------------------------------------------------------------------------
// Kernel 4: cp.async 3-stage pipelined HMMA GEMM.
// 256 thr = 8 warps (2m x 4n), CTA tile 128x128, stage = 4 ksteps.
// Stage smem: A [mt 8][ks 4][slot 32]u4 (16KB) then B [nt 16][ks 4][16]u4.
// ---------------------------------------------------------------------------
__global__ __launch_bounds__(256, 2) void kan_mma_kernel(
    const float* __restrict__ bias, float* __restrict__ out)
{
    extern __shared__ __align__(16) char smem[];
    const uint32_t sbase = smem_u32(smem);

    const int tid  = threadIdx.x;
    const int lane = tid & 31;
    const int wid  = tid >> 5;
    const int wm   = wid >> 2;
    const int wn   = wid & 3;
    const int row0 = blockIdx.y * 128;
    const int col0 = blockIdx.x * 128;

    // gmem frag sources (uint4 units)
    const uint4* agm = reinterpret_cast<const uint4*>(g_af);
    const uint4* bgm = reinterpret_cast<const uint4*>(g_btf);
    const size_t arow0 = (size_t)blockIdx.y * 8;   // mt rows base
    const size_t brow0 = (size_t)blockIdx.x * 16;  // nt rows base

    // copy coords: 4 A-uint4 + 4 B-uint4 per thread per stage
    // A: q = tid + r*256 -> mt=q>>7, ks=(q>>5)&3, l=q&31
    // B: q -> nt=q>>6, ks=(q>>4)&3, i=q&15
    auto issue_stage = [&](int stg, int ks0) {
        const uint32_t da = sbase + stg * STG_BYTES;
        const uint32_t db = da + 16384;
        #pragma unroll
        for (int r = 0; r < 4; ++r) {
            int q = tid + r * 256;
            const uint4* srcA = agm +
                ((arow0 + (q >> 7)) * NKSTEP + ks0 + ((q >> 5) & 3)) * 32 + (q & 31);
            CP_ASYNC16(da + q * 16, srcA);
        }
        #pragma unroll
        for (int r = 0; r < 4; ++r) {
            int q = tid + r * 256;
            const uint4* srcB = bgm +
                ((brow0 + (q >> 6)) * NKSTEP + ks0 + ((q >> 4) & 3)) * 16 + (q & 15);
            CP_ASYNC16(db + q * 16, srcB);
        }
        CP_COMMIT();
    };

    // acc init = bias
    float acc[4][4][4];
    #pragma unroll
    for (int in = 0; in < 4; ++in) {
        float2 bb = *reinterpret_cast<const float2*>(
            bias + col0 + wn * 32 + in * 8 + (lane & 3) * 2);
        #pragma unroll
        for (int im = 0; im < 4; ++im) {
            acc[im][in][0] = bb.x; acc[im][in][1] = bb.y;
            acc[im][in][2] = bb.x; acc[im][in][3] = bb.y;
        }
    }

    issue_stage(0, 0);
    issue_stage(1, BIG);

    const int aslot = SIG(lane);
    int stg = 0;
    for (int it = 0; it < NIT; ++it) {
        CP_WAIT1();
        __syncthreads();
        if (it + 2 < NIT) issue_stage((stg + 2) % NSTG, (it + 2) * BIG);

        const char* sa = smem + stg * STG_BYTES;
        const char* sb = sa + 16384;
        #pragma unroll
        for (int ks = 0; ks < BIG; ++ks) {
            uint4 a[4];
            #pragma unroll
            for (int im = 0; im < 4; ++im)
                a[im] = *reinterpret_cast<const uint4*>(
                    sa + (((wm * 4 + im) * 4 + ks) * 32 + aslot) * 16);
            uint2 b[4];
            #pragma unroll
            for (int in = 0; in < 4; ++in)
                b[in] = *reinterpret_cast<const uint2*>(
                    sb + (((wn * 4 + in) * 4 + ks) * 32 + lane) * 8);
            #pragma unroll
            for (int im = 0; im < 4; ++im)
                #pragma unroll
                for (int in = 0; in < 4; ++in) {
                    asm volatile(
                        "mma.sync.aligned.m16n8k16.row.col.f32.f16.f16.f32 "
                        "{%0,%1,%2,%3}, {%4,%5,%6,%7}, {%8,%9}, {%0,%1,%2,%3};"
                        : "+f"(acc[im][in][0]), "+f"(acc[im][in][1]),
                          "+f"(acc[im][in][2]), "+f"(acc[im][in][3])
                        : "r"(a[im].x), "r"(a[im].y), "r"(a[im].z), "r"(a[im].w),
                          "r"(b[in].x), "r"(b[in].y));
                }
        }
        __syncthreads();
        stg = (stg + 1) % NSTG;
    }

    // epilogue (unchanged, passing)
    const int g  = lane >> 2;
    const int tq = lane & 3;
    #pragma unroll
    for (int im = 0; im < 4; ++im) {
        int row = row0 + wm * 64 + im * 16 + g;
        #pragma unroll
        for (int in = 0; in < 4; ++in) {
            int col = col0 + wn * 32 + in * 8 + tq * 2;
            *reinterpret_cast<float2*>(out + (size_t)row * UDIM + col)
                = make_float2(acc[im][in][0], acc[im][in][1]);
            *reinterpret_cast<float2*>(out + (size_t)(row + 8) * UDIM + col)
                = make_float2(acc[im][in][2], acc[im][in][3]);
        }
    }
}

// ---------------------------------------------------------------------------
extern "C" void kernel_launch(void* const* d_in, const int* in_sizes, int n_in,
                              void* d_out, int out_size) {
    const float* x     = (const float*)d_in[0];
    const float* gamma = (const float*)d_in[1];
    const float* beta  = (const float*)d_in[2];
    const float* Wb    = (const float*)d_in[3];
    const float* bias  = (const float*)d_in[4];
    const float* Ws    = (const float*)d_in[5];
    const float* grid  = (const float*)d_in[6];
    float* out = (float*)d_out;

    cudaFuncSetAttribute(kan_mma_kernel,
                         cudaFuncAttributeMaxDynamicSharedMemorySize, SMEM_TOTAL);

    ln_kernel<<<NROWS, 128>>>(x, gamma, beta);
    btf_kernel<<<1024, 256>>>(Wb, Ws);
    af_kernel<<<dim3(AF_CG, NROWS / 128), 256>>>(grid);
    kan_mma_kernel<<<dim3(UDIM / 128, NROWS / 128), 256, SMEM_TOTAL>>>(bias, out);
}

// round 10
// speedup vs baseline: 8.3826x; 1.0286x over previous
#include <cuda_runtime.h>
#include <cuda_fp16.h>
#include <cstdint>

// KANLinear, round 10: (1) GEMM multistage loop with ONE barrier per
// k-iteration (trailing sync removed — writes after the top barrier only
// touch a stage no warp is reading); (2) af_kernel with smem-staged,
// coalesced x loads and 2x grid parallelism. GEMM math/layouts unchanged.

#define NROWS 32768
#define FDIM  512
#define UDIM  512
#define NCHUNK 128
#define NKSTEP 256
#define AF_CG  16
#define AF_CPB (NCHUNK / AF_CG)     // 8 chunks per af block

#define BIG    4                    // ksteps per stage
#define NIT    (NKSTEP / BIG)       // 64
#define STG_BYTES 32768             // 16KB A + 16KB B
#define NSTG   3
#define SMEM_TOTAL (NSTG * STG_BYTES)

__device__ float  g_xn [(size_t)NROWS * FDIM];            // 64 MB LN output
__device__ __half g_btf[(size_t)64 * NKSTEP * 32 * 4];    // 4 MB B frags
__device__ __half g_af [(size_t)2048 * NKSTEP * 32 * 8];  // 256 MB A frags

#define SIG(L) ((((L) & 3) << 3) | (((L) >> 2) ^ ((((L) & 3) << 1) & 7)))

__device__ __forceinline__ uint32_t smem_u32(const void* p) {
    uint32_t a;
    asm("{ .reg .u64 t; cvta.to.shared.u64 t, %1; cvt.u32.u64 %0, t; }"
        : "=r"(a) : "l"(p));
    return a;
}
#define CP_ASYNC16(dst_u32, src_ptr) \
    asm volatile("cp.async.cg.shared.global [%0], [%1], 16;" \
                 :: "r"(dst_u32), "l"(src_ptr) : "memory")
#define CP_COMMIT() asm volatile("cp.async.commit_group;" ::: "memory")
#define CP_WAIT1()  asm volatile("cp.async.wait_group 1;" ::: "memory")

// ---------------------------------------------------------------------------
// Kernel 1: LayerNorm (unchanged, passing)
// ---------------------------------------------------------------------------
__global__ __launch_bounds__(128) void ln_kernel(const float* __restrict__ x,
                                                 const float* __restrict__ gamma,
                                                 const float* __restrict__ beta) {
    int row = blockIdx.x, tid = threadIdx.x;
    const float4* xr = reinterpret_cast<const float4*>(x + (size_t)row * FDIM);
    float4 v = xr[tid];
    __shared__ float red[4], red2[4];
    float s = v.x + v.y + v.z + v.w;
    #pragma unroll
    for (int o = 16; o > 0; o >>= 1) s += __shfl_xor_sync(~0u, s, o);
    if ((tid & 31) == 0) red[tid >> 5] = s;
    __syncthreads();
    float mean = (red[0] + red[1] + red[2] + red[3]) * (1.0f / FDIM);
    float dx = v.x - mean, dy = v.y - mean, dz = v.z - mean, dw = v.w - mean;
    float s2 = dx * dx + dy * dy + dz * dz + dw * dw;
    #pragma unroll
    for (int o = 16; o > 0; o >>= 1) s2 += __shfl_xor_sync(~0u, s2, o);
    if ((tid & 31) == 0) red2[tid >> 5] = s2;
    __syncthreads();
    float inv = rsqrtf((red2[0] + red2[1] + red2[2] + red2[3]) * (1.0f / FDIM) + 1e-3f);
    float4 g = reinterpret_cast<const float4*>(gamma)[tid];
    float4 b = reinterpret_cast<const float4*>(beta)[tid];
    float4 o4 = { dx * inv * g.x + b.x, dy * inv * g.y + b.y,
                  dz * inv * g.z + b.z, dw * inv * g.w + b.w };
    reinterpret_cast<float4*>(g_xn + (size_t)row * FDIM)[tid] = o4;
}

// ---------------------------------------------------------------------------
// Kernel 2: B fragments (unchanged, passing)
// ---------------------------------------------------------------------------
__global__ __launch_bounds__(256) void btf_kernel(const float* __restrict__ Wb,
                                                  const float* __restrict__ Ws) {
    int bid = blockIdx.x, t = threadIdx.x;
    int f = bid >> 1;
    int n = ((bid & 1) << 8) + t;
    float w[8];
    w[0] = Wb[(size_t)f * UDIM + n];
    #pragma unroll
    for (int m = 1; m <= 6; ++m)
        w[m] = Ws[(size_t)(f * 6 + m - 1) * UDIM + n];
    w[7] = 0.0f;
    __half2* dst = reinterpret_cast<__half2*>(g_btf);
    size_t s = ((size_t)(n >> 3) * 256 + (f >> 1)) * 32 + (n & 7) * 4;
    #pragma unroll
    for (int mp = 0; mp < 4; ++mp)
        dst[(s + mp) * 2 + (f & 1)] = __floats2half2_rn(w[2 * mp], w[2 * mp + 1]);
}

// ---------------------------------------------------------------------------
// closed-form cubic B-spline (unchanged, passing)
// ---------------------------------------------------------------------------
__device__ __forceinline__ void gen8(float xv, float t0, float inv_h, float* v) {
    float xr = (xv - t0) * inv_h;
    float fi = floorf(xr);
    int   i  = (int)fi;
    float s  = xr - fi;
    float s2 = s * s, s3 = s2 * s;
    float u  = 1.0f - s;
    const float c6 = 1.0f / 6.0f;
    float B0 = c6 * u * u * u;
    float B1 = c6 * (3.0f * s3 - 6.0f * s2 + 4.0f);
    float B2 = c6 * (-3.0f * s3 + 3.0f * s2 + 3.0f * s + 1.0f);
    float B3 = c6 * s3;
    bool valid = (xr >= 0.0f) && (i <= 8);
    v[0] = fmaxf(xv, 0.0f);
    #pragma unroll
    for (int j = 0; j < 6; ++j) {
        int d = i - j;
        float bv = (d == 3) ? B0 : (d == 2) ? B1 : (d == 1) ? B2 : (d == 0) ? B3 : 0.0f;
        v[1 + j] = valid ? bv : 0.0f;
    }
    v[7] = 0.0f;
}

// ---------------------------------------------------------------------------
// Kernel 3: A fragments -> gmem. Grid (16 chunk-groups, 256 row-blocks).
// x tile staged through smem with coalesced loads; frag indexing identical
// to the passing round-8/9 version.
// ---------------------------------------------------------------------------
__global__ __launch_bounds__(256) void af_kernel(const float* __restrict__ grid_knots) {
    __shared__ float sx[128][34];                 // 32 feats + pad (8B-aligned f2)
    __shared__ __align__(16) char st[2][8192];
    const int tid = threadIdx.x;
    const float t0    = __ldg(grid_knots);
    const float inv_h = 1.0f / (__ldg(grid_knots + 1) - t0);

    const int c0 = blockIdx.x * AF_CPB;           // first chunk of this group
    const int rb = blockIdx.y;                    // row-block

    // ---- stage x: 128 rows x 32 feats, coalesced float4 loads ----
    for (int idx = tid; idx < 128 * 8; idx += 256) {
        int row = idx >> 3, qc = idx & 7;
        float4 v = __ldg(reinterpret_cast<const float4*>(
            g_xn + (size_t)(rb * 128 + row) * FDIM + c0 * 4) + qc);
        *reinterpret_cast<float2*>(&sx[row][qc * 4])     = make_float2(v.x, v.y);
        *reinterpret_cast<float2*>(&sx[row][qc * 4 + 2]) = make_float2(v.z, v.w);
    }
    __syncthreads();

    const int gr = tid >> 1;
    const int gh = tid & 1;
    const int mt = gr >> 4;
    const int g7 = gr & 7;
    const int hi = (gr >> 3) & 1;

    const int mtc = tid >> 5;
    const int ghc = (tid >> 4) & 1;
    const int qo  = (tid & 15) * 2;
    const size_t mtG0 = (size_t)rb * 8;

    #pragma unroll 1
    for (int cc = 0; cc < AF_CPB; ++cc) {
        const int c   = c0 + cc;
        const int buf = cc & 1;
        float2 xv = *reinterpret_cast<const float2*>(&sx[gr][cc * 4 + gh * 2]);
        float vE[8], vO[8];
        gen8(xv.x, t0, inv_h, vE);
        gen8(xv.y, t0, inv_h, vO);
        char* ab = st[buf] + (mt * 2 + gh) * 512;
        #pragma unroll
        for (int t = 0; t < 4; ++t) {
            int L = g7 * 4 + t;
            int off = SIG(L) * 16 + hi * 4;
            *reinterpret_cast<__half2*>(ab + off) =
                __floats2half2_rn(vE[2 * t], vE[2 * t + 1]);
            *reinterpret_cast<__half2*>(ab + off + 8) =
                __floats2half2_rn(vO[2 * t], vO[2 * t + 1]);
        }
        __syncthreads();
        {
            const uint4* src = reinterpret_cast<const uint4*>(
                st[buf] + (mtc * 2 + ghc) * 512) + qo;
            uint4* dst = reinterpret_cast<uint4*>(g_af) +
                ((mtG0 + mtc) * NKSTEP + (c * 2 + ghc)) * 32 + qo;
            dst[0] = src[0];
            dst[1] = src[1];
        }
    }
}

// ---------------------------------------------------------------------------
// Kernel 4: cp.async 3-stage pipelined HMMA GEMM — ONE barrier per iteration.
// ---------------------------------------------------------------------------
__global__ __launch_bounds__(256, 2) void kan_mma_kernel(
    const float* __restrict__ bias, float* __restrict__ out)
{
    extern __shared__ __align__(16) char smem[];
    const uint32_t sbase = smem_u32(smem);

    const int tid  = threadIdx.x;
    const int lane = tid & 31;
    const int wid  = tid >> 5;
    const int wm   = wid >> 2;
    const int wn   = wid & 3;
    const int row0 = blockIdx.y * 128;
    const int col0 = blockIdx.x * 128;

    const uint4* agm = reinterpret_cast<const uint4*>(g_af);
    const uint4* bgm = reinterpret_cast<const uint4*>(g_btf);
    const size_t arow0 = (size_t)blockIdx.y * 8;
    const size_t brow0 = (size_t)blockIdx.x * 16;

    auto issue_stage = [&](int stg, int ks0) {
        const uint32_t da = sbase + stg * STG_BYTES;
        const uint32_t db = da + 16384;
        #pragma unroll
        for (int r = 0; r < 4; ++r) {
            int q = tid + r * 256;
            const uint4* srcA = agm +
                ((arow0 + (q >> 7)) * NKSTEP + ks0 + ((q >> 5) & 3)) * 32 + (q & 31);
            CP_ASYNC16(da + q * 16, srcA);
        }
        #pragma unroll
        for (int r = 0; r < 4; ++r) {
            int q = tid + r * 256;
            const uint4* srcB = bgm +
                ((brow0 + (q >> 6)) * NKSTEP + ks0 + ((q >> 4) & 3)) * 16 + (q & 15);
            CP_ASYNC16(db + q * 16, srcB);
        }
        CP_COMMIT();
    };

    float acc[4][4][4];
    #pragma unroll
    for (int in = 0; in < 4; ++in) {
        float2 bb = *reinterpret_cast<const float2*>(
            bias + col0 + wn * 32 + in * 8 + (lane & 3) * 2);
        #pragma unroll
        for (int im = 0; im < 4; ++im) {
            acc[im][in][0] = bb.x; acc[im][in][1] = bb.y;
            acc[im][in][2] = bb.x; acc[im][in][3] = bb.y;
        }
    }

    issue_stage(0, 0);
    issue_stage(1, BIG);

    const int aslot = SIG(lane);
    int stg = 0;
    for (int it = 0; it < NIT; ++it) {
        CP_WAIT1();
        __syncthreads();
        // Safe to fill (stg+2)%3 == (stg-1)%3: every warp passed the barrier,
        // so all reads from that stage (previous iteration) are complete.
        if (it + 2 < NIT) issue_stage((stg + 2) % NSTG, (it + 2) * BIG);

        const char* sa = smem + stg * STG_BYTES;
        const char* sb = sa + 16384;
        #pragma unroll
        for (int ks = 0; ks < BIG; ++ks) {
            uint4 a[4];
            #pragma unroll
            for (int im = 0; im < 4; ++im)
                a[im] = *reinterpret_cast<const uint4*>(
                    sa + (((wm * 4 + im) * 4 + ks) * 32 + aslot) * 16);
            uint2 b[4];
            #pragma unroll
            for (int in = 0; in < 4; ++in)
                b[in] = *reinterpret_cast<const uint2*>(
                    sb + (((wn * 4 + in) * 4 + ks) * 32 + lane) * 8);
            #pragma unroll
            for (int im = 0; im < 4; ++im)
                #pragma unroll
                for (int in = 0; in < 4; ++in) {
                    asm volatile(
                        "mma.sync.aligned.m16n8k16.row.col.f32.f16.f16.f32 "
                        "{%0,%1,%2,%3}, {%4,%5,%6,%7}, {%8,%9}, {%0,%1,%2,%3};"
                        : "+f"(acc[im][in][0]), "+f"(acc[im][in][1]),
                          "+f"(acc[im][in][2]), "+f"(acc[im][in][3])
                        : "r"(a[im].x), "r"(a[im].y), "r"(a[im].z), "r"(a[im].w),
                          "r"(b[in].x), "r"(b[in].y));
                }
        }
        stg = (stg + 1) % NSTG;
    }

    const int g  = lane >> 2;
    const int tq = lane & 3;
    #pragma unroll
    for (int im = 0; im < 4; ++im) {
        int row = row0 + wm * 64 + im * 16 + g;
        #pragma unroll
        for (int in = 0; in < 4; ++in) {
            int col = col0 + wn * 32 + in * 8 + tq * 2;
            *reinterpret_cast<float2*>(out + (size_t)row * UDIM + col)
                = make_float2(acc[im][in][0], acc[im][in][1]);
            *reinterpret_cast<float2*>(out + (size_t)(row + 8) * UDIM + col)
                = make_float2(acc[im][in][2], acc[im][in][3]);
        }
    }
}

// ---------------------------------------------------------------------------
extern "C" void kernel_launch(void* const* d_in, const int* in_sizes, int n_in,
                              void* d_out, int out_size) {
    const float* x     = (const float*)d_in[0];
    const float* gamma = (const float*)d_in[1];
    const float* beta  = (const float*)d_in[2];
    const float* Wb    = (const float*)d_in[3];
    const float* bias  = (const float*)d_in[4];
    const float* Ws    = (const float*)d_in[5];
    const float* grid  = (const float*)d_in[6];
    float* out = (float*)d_out;

    cudaFuncSetAttribute(kan_mma_kernel,
                         cudaFuncAttributeMaxDynamicSharedMemorySize, SMEM_TOTAL);

    ln_kernel<<<NROWS, 128>>>(x, gamma, beta);
    btf_kernel<<<1024, 256>>>(Wb, Ws);
    af_kernel<<<dim3(AF_CG, NROWS / 128), 256>>>(grid);
    kan_mma_kernel<<<dim3(UDIM / 128, NROWS / 128), 256, SMEM_TOTAL>>>(bias, out);
}